// round 1
// baseline (speedup 1.0000x reference)
#include <cuda_runtime.h>
#include <math.h>

// Problem constants
#define T_ROWS   8192            // B*N
#define C_DIM    1024
#define H_DIM    16
#define D_DIM    64
#define FUSED_N  7168            // 3C + MLP
#define SE_N     2048
#define MLP_DIM  4096
#define INNER    2730
#define INNER_P  2736            // padded to multiple of 8/16
#define VG_N     5460            // 2*INNER

// ---------------- scratch (static device allocations) ----------------
__device__ float g_se   [T_ROWS * SE_N];                 // emb modulation
__device__ float g_xn   [T_ROWS * C_DIM];                // modulated LN(x)
__device__ float g_fused[(size_t)T_ROWS * FUSED_N];      // q|k|v|mlp_h (q,k LN'd in place)
__device__ float g_o    [T_ROWS * C_DIM];                // attention out [B,N,H,D]
__device__ float g_vg   [(size_t)T_ROWS * VG_N];
__device__ float g_h2   [(size_t)T_ROWS * INNER_P];      // silu(g)*vv, zero padded
__device__ float g_Wmo  [INNER_P * C_DIM];               // padded Wm_out
__device__ float g_f    [T_ROWS * C_DIM];                // f (pre norm) [B,N,H,D]
__device__ float g_gate [T_ROWS * H_DIM];
__device__ float g_rms  [4 * H_DIM];
__device__ float g_x2   [T_ROWS * C_DIM];

// ---------------- generic 128x128x8 SGEMM ----------------
// C[M,N] = epilogue( A[M,K](opt silu) * B[K,N] + bias[N] (+ R[M,N]) )
// M = gridDim.y*128 (always multiple of 128 here), N arbitrary (mult of 4),
// K multiple of 8.
template<bool SILU_A, bool RESID>
__global__ void __launch_bounds__(256) sgemm_k(
    const float* __restrict__ A, int lda,
    const float* __restrict__ B, int ldb,
    const float* __restrict__ bias,
    const float* __restrict__ R, int ldr,
    float* __restrict__ C, int ldc,
    int N, int K)
{
    __shared__ float As[8][128];
    __shared__ float Bs[8][128];
    const int tid = threadIdx.x;
    const int bx = blockIdx.x, by = blockIdx.y;
    const int tx = tid & 15, ty = tid >> 4;

    const int ar = tid >> 1;          // A tile row 0..127
    const int ac = (tid & 1) * 4;     // A tile col 0 or 4
    const int br = tid >> 5;          // B tile row 0..7
    const int bc = (tid & 31) * 4;    // B tile col
    const int gnl = bx * 128 + bc;

    const float* Ap = A + (size_t)(by * 128 + ar) * lda + ac;
    const float* Bp = B + (size_t)br * ldb + gnl;

    float acc[8][8];
#pragma unroll
    for (int i = 0; i < 8; i++)
#pragma unroll
        for (int j = 0; j < 8; j++) acc[i][j] = 0.f;

    for (int k0 = 0; k0 < K; k0 += 8) {
        float4 a4 = *(const float4*)(Ap + k0);
        if (SILU_A) {
            a4.x = a4.x / (1.f + __expf(-a4.x));
            a4.y = a4.y / (1.f + __expf(-a4.y));
            a4.z = a4.z / (1.f + __expf(-a4.z));
            a4.w = a4.w / (1.f + __expf(-a4.w));
        }
        As[ac + 0][ar] = a4.x;
        As[ac + 1][ar] = a4.y;
        As[ac + 2][ar] = a4.z;
        As[ac + 3][ar] = a4.w;
        float4 b4 = make_float4(0.f, 0.f, 0.f, 0.f);
        if (gnl < N) b4 = *(const float4*)(Bp + (size_t)k0 * ldb);
        *(float4*)&Bs[br][bc] = b4;
        __syncthreads();
#pragma unroll
        for (int kk = 0; kk < 8; kk++) {
            float av[8], bv[8];
            *(float4*)&av[0] = *(const float4*)&As[kk][ty * 8];
            *(float4*)&av[4] = *(const float4*)&As[kk][ty * 8 + 4];
            *(float4*)&bv[0] = *(const float4*)&Bs[kk][tx * 8];
            *(float4*)&bv[4] = *(const float4*)&Bs[kk][tx * 8 + 4];
#pragma unroll
            for (int i = 0; i < 8; i++)
#pragma unroll
                for (int j = 0; j < 8; j++)
                    acc[i][j] += av[i] * bv[j];
        }
        __syncthreads();
    }

#pragma unroll
    for (int i = 0; i < 8; i++) {
        const int gm = by * 128 + ty * 8 + i;
#pragma unroll
        for (int j = 0; j < 8; j += 4) {
            const int gn = bx * 128 + tx * 8 + j;
            if (gn < N) {
                float4 out;
                out.x = acc[i][j + 0] + bias[gn + 0];
                out.y = acc[i][j + 1] + bias[gn + 1];
                out.z = acc[i][j + 2] + bias[gn + 2];
                out.w = acc[i][j + 3] + bias[gn + 3];
                if (RESID) {
                    float4 r4 = *(const float4*)(R + (size_t)gm * ldr + gn);
                    out.x += r4.x; out.y += r4.y; out.z += r4.z; out.w += r4.w;
                }
                *(float4*)(C + (size_t)gm * ldc + gn) = out;
            }
        }
    }
}

// ---------------- block reduce helper ----------------
__device__ __forceinline__ float block_reduce_sum(float v)
{
    __shared__ float sh[32];
    const int lane = threadIdx.x & 31, wid = threadIdx.x >> 5;
#pragma unroll
    for (int o = 16; o > 0; o >>= 1) v += __shfl_xor_sync(0xffffffffu, v, o);
    __syncthreads();
    if (lane == 0) sh[wid] = v;
    __syncthreads();
    const int nw = blockDim.x >> 5;
    float r = (threadIdx.x < nw) ? sh[threadIdx.x] : 0.f;
    if (wid == 0) {
#pragma unroll
        for (int o = 16; o > 0; o >>= 1) r += __shfl_xor_sync(0xffffffffu, r, o);
        if (lane == 0) sh[0] = r;
    }
    __syncthreads();
    return sh[0];
}

// ---------------- LN(x)*(1+scale)+shift ----------------
__global__ void __launch_bounds__(256) k_lnmod(
    const float* __restrict__ x, const float* __restrict__ lnw,
    const float* __restrict__ lnb, const float* __restrict__ se,
    float* __restrict__ xn)
{
    const int r = blockIdx.x, tid = threadIdx.x;
    const float4 v = ((const float4*)(x + (size_t)r * C_DIM))[tid];
    float s = v.x + v.y + v.z + v.w;
    s = block_reduce_sum(s);
    const float mu = s * (1.f / 1024.f);
    const float dx0 = v.x - mu, dx1 = v.y - mu, dx2 = v.z - mu, dx3 = v.w - mu;
    float q = dx0 * dx0 + dx1 * dx1 + dx2 * dx2 + dx3 * dx3;
    q = block_reduce_sum(q);
    const float rstd = rsqrtf(q * (1.f / 1024.f) + 1e-5f);
    const float4 w = ((const float4*)lnw)[tid];
    const float4 bb = ((const float4*)lnb)[tid];
    const float4 sc = ((const float4*)(se + (size_t)r * SE_N))[tid];
    const float4 sf = ((const float4*)(se + (size_t)r * SE_N + C_DIM))[tid];
    float4 out;
    out.x = (dx0 * rstd * w.x + bb.x) * (1.f + sc.x) + sf.x;
    out.y = (dx1 * rstd * w.y + bb.y) * (1.f + sc.y) + sf.y;
    out.z = (dx2 * rstd * w.z + bb.z) * (1.f + sc.z) + sf.z;
    out.w = (dx3 * rstd * w.w + bb.w) * (1.f + sc.w) + sf.w;
    ((float4*)(xn + (size_t)r * C_DIM))[tid] = out;
}

// ---------------- per-head LN of q,k (in place in fused) ----------------
__global__ void __launch_bounds__(256) k_qkln(
    float* __restrict__ fused,
    const float* __restrict__ qw, const float* __restrict__ qb,
    const float* __restrict__ kw, const float* __restrict__ kb)
{
    const int w = threadIdx.x >> 5, lane = threadIdx.x & 31;
    const int idx = blockIdx.x * 8 + w;       // 0..131071 (r,h pairs)
    const int r = idx >> 4, h = idx & 15;
    float* base = fused + (size_t)r * FUSED_N + h * D_DIM;
#pragma unroll
    for (int part = 0; part < 2; part++) {
        float* p = base + part * C_DIM;
        float v0 = p[lane], v1 = p[lane + 32];
        float s = v0 + v1;
#pragma unroll
        for (int o = 16; o > 0; o >>= 1) s += __shfl_xor_sync(0xffffffffu, s, o);
        const float mu = s * (1.f / 64.f);
        const float d0 = v0 - mu, d1 = v1 - mu;
        float q = d0 * d0 + d1 * d1;
#pragma unroll
        for (int o = 16; o > 0; o >>= 1) q += __shfl_xor_sync(0xffffffffu, q, o);
        const float rstd = rsqrtf(q * (1.f / 64.f) + 1e-5f);
        const float* ww = part ? kw : qw;
        const float* bb = part ? kb : qb;
        p[lane]      = d0 * rstd * ww[lane]      + bb[lane];
        p[lane + 32] = d1 * rstd * ww[lane + 32] + bb[lane + 32];
    }
}

// ---------------- flash attention, fp32, 64x64 tiles ----------------
#define APAD 68
__global__ void __launch_bounds__(256) k_attn(
    const float* __restrict__ fused, float* __restrict__ o)
{
    extern __shared__ float sh[];
    float* Qs = sh;                      // [64][68] (d-major)
    float* Ks = sh + 64 * APAD;          // [64][68] (d-major)
    float* Vs = sh + 2 * 64 * APAD;      // [64][68] (j-major)
    float* Ps = sh + 3 * 64 * APAD;      // [64][68]

    const int qt = blockIdx.x;           // 0..31
    const int bh = blockIdx.y;           // 0..63
    const int b = bh >> 4, h = bh & 15;
    const int tid = threadIdx.x;
    const int tx = tid & 15, ty = tid >> 4;

    const float* qbase = fused + (size_t)(b * 2048 + qt * 64) * FUSED_N + h * D_DIM;
    for (int idx = tid; idx < 4096; idx += 256) {
        const int i = idx >> 6, d = idx & 63;
        Qs[d * APAD + i] = qbase[(size_t)i * FUSED_N + d] * 0.125f;
    }

    float m[4], l[4], oa[4][4];
#pragma unroll
    for (int ii = 0; ii < 4; ii++) {
        m[ii] = -1e30f; l[ii] = 0.f;
#pragma unroll
        for (int dd = 0; dd < 4; dd++) oa[ii][dd] = 0.f;
    }
    __syncthreads();

    for (int kt = 0; kt < 32; kt++) {
        const float* kbase = fused + (size_t)(b * 2048 + kt * 64) * FUSED_N + C_DIM + h * D_DIM;
        const float* vbase = kbase + C_DIM;
        for (int idx = tid; idx < 4096; idx += 256) {
            const int j = idx >> 6, d = idx & 63;
            Ks[d * APAD + j] = kbase[(size_t)j * FUSED_N + d];
            Vs[j * APAD + d] = vbase[(size_t)j * FUSED_N + d];
        }
        __syncthreads();

        float s[4][4];
#pragma unroll
        for (int ii = 0; ii < 4; ii++)
#pragma unroll
            for (int jj = 0; jj < 4; jj++) s[ii][jj] = 0.f;

#pragma unroll 16
        for (int d = 0; d < 64; d++) {
            const float4 a  = *(const float4*)&Qs[d * APAD + ty * 4];
            const float4 bq = *(const float4*)&Ks[d * APAD + tx * 4];
            const float av[4] = {a.x, a.y, a.z, a.w};
            const float bv[4] = {bq.x, bq.y, bq.z, bq.w};
#pragma unroll
            for (int ii = 0; ii < 4; ii++)
#pragma unroll
                for (int jj = 0; jj < 4; jj++)
                    s[ii][jj] += av[ii] * bv[jj];
        }

#pragma unroll
        for (int ii = 0; ii < 4; ii++) {
            float rm = fmaxf(fmaxf(s[ii][0], s[ii][1]), fmaxf(s[ii][2], s[ii][3]));
#pragma unroll
            for (int off = 1; off < 16; off <<= 1)
                rm = fmaxf(rm, __shfl_xor_sync(0xffffffffu, rm, off));
            const float mn = fmaxf(m[ii], rm);
            const float alpha = __expf(m[ii] - mn);
            m[ii] = mn;
            float rs = 0.f;
#pragma unroll
            for (int jj = 0; jj < 4; jj++) {
                const float p = __expf(s[ii][jj] - mn);
                s[ii][jj] = p; rs += p;
            }
#pragma unroll
            for (int off = 1; off < 16; off <<= 1)
                rs += __shfl_xor_sync(0xffffffffu, rs, off);
            l[ii] = l[ii] * alpha + rs;
#pragma unroll
            for (int dd = 0; dd < 4; dd++) oa[ii][dd] *= alpha;
        }

#pragma unroll
        for (int ii = 0; ii < 4; ii++)
            *(float4*)&Ps[(ty * 4 + ii) * APAD + tx * 4] =
                make_float4(s[ii][0], s[ii][1], s[ii][2], s[ii][3]);
        __syncthreads();

#pragma unroll 4
        for (int j4 = 0; j4 < 16; j4++) {
            float4 pv[4], vr[4];
#pragma unroll
            for (int ii = 0; ii < 4; ii++)
                pv[ii] = *(const float4*)&Ps[(ty * 4 + ii) * APAD + j4 * 4];
#pragma unroll
            for (int jj = 0; jj < 4; jj++)
                vr[jj] = *(const float4*)&Vs[(j4 * 4 + jj) * APAD + tx * 4];
#pragma unroll
            for (int ii = 0; ii < 4; ii++) {
                oa[ii][0] += pv[ii].x * vr[0].x + pv[ii].y * vr[1].x + pv[ii].z * vr[2].x + pv[ii].w * vr[3].x;
                oa[ii][1] += pv[ii].x * vr[0].y + pv[ii].y * vr[1].y + pv[ii].z * vr[2].y + pv[ii].w * vr[3].y;
                oa[ii][2] += pv[ii].x * vr[0].z + pv[ii].y * vr[1].z + pv[ii].z * vr[2].z + pv[ii].w * vr[3].z;
                oa[ii][3] += pv[ii].x * vr[0].w + pv[ii].y * vr[1].w + pv[ii].z * vr[2].w + pv[ii].w * vr[3].w;
            }
        }
        __syncthreads();
    }

    float* obase = o + (size_t)(b * 2048 + qt * 64) * C_DIM + h * D_DIM;
#pragma unroll
    for (int ii = 0; ii < 4; ii++) {
        const float inv = 1.f / l[ii];
        *(float4*)&obase[(size_t)(ty * 4 + ii) * C_DIM + tx * 4] =
            make_float4(oa[ii][0] * inv, oa[ii][1] * inv, oa[ii][2] * inv, oa[ii][3] * inv);
    }
}

// ---------------- h2 = silu(g)*vv, zero padded ----------------
__global__ void __launch_bounds__(256) k_silu_h2(
    const float* __restrict__ vg, float* __restrict__ h2)
{
    const int r = blockIdx.x;
    const float* vr = vg + (size_t)r * VG_N;
    float* hr = h2 + (size_t)r * INNER_P;
    for (int c = threadIdx.x; c < INNER_P; c += 256) {
        float out = 0.f;
        if (c < INNER) {
            const float vv = vr[c];
            const float g = vr[INNER + c];
            out = vv * g / (1.f + __expf(-g));
        }
        hr[c] = out;
    }
}

// ---------------- pad Wm_out to 2736 rows ----------------
__global__ void __launch_bounds__(256) k_padW(const float* __restrict__ W, float* __restrict__ Wp)
{
    const int row = blockIdx.x;
    for (int c = threadIdx.x; c < C_DIM; c += 256)
        Wp[(size_t)row * C_DIM + c] = (row < INNER) ? W[(size_t)row * C_DIM + c] : 0.f;
}

// ---------------- gate = tanh(x @ W_g + b_g) ----------------
__global__ void __launch_bounds__(256) k_gate(
    const float* __restrict__ x, const float* __restrict__ Wg,
    const float* __restrict__ bg, float* __restrict__ gate)
{
    __shared__ float xs[1024];
    __shared__ float part[16][17];
    const int r = blockIdx.x, tid = threadIdx.x;
    *(float4*)&xs[tid * 4] = ((const float4*)(x + (size_t)r * C_DIM))[tid];
    __syncthreads();
    const int h = tid & 15, seg = tid >> 4;
    float s = 0.f;
#pragma unroll 8
    for (int c = seg * 64; c < seg * 64 + 64; c++) s += xs[c] * Wg[c * 16 + h];
    part[h][seg] = s;
    __syncthreads();
    if (tid < 16) {
        float t = bg[tid];
#pragma unroll
        for (int sg = 0; sg < 16; sg++) t += part[tid][sg];
        gate[(size_t)r * 16 + tid] = tanhf(t);
    }
}

// ---------------- rms[b,h] over (n,d) of f ----------------
__global__ void __launch_bounds__(256) k_rms(const float* __restrict__ f, float* __restrict__ rms)
{
    const int b = blockIdx.x >> 4, h = blockIdx.x & 15;
    float s = 0.f;
    for (int n = threadIdx.x; n < 2048; n += 256) {
        const float4* fp = (const float4*)(f + (size_t)(b * 2048 + n) * C_DIM + h * D_DIM);
#pragma unroll
        for (int d4 = 0; d4 < 16; d4++) {
            const float4 v = fp[d4];
            s += v.x * v.x + v.y * v.y + v.z * v.z + v.w * v.w;
        }
    }
    s = block_reduce_sum(s);
    if (threadIdx.x == 0)
        rms[blockIdx.x] = fmaxf(sqrtf(s * (1.f / 131072.f)), 1e-6f);
}

// ---------------- o += gate * f / rms ----------------
__global__ void __launch_bounds__(256) k_combine(
    float* __restrict__ o, const float* __restrict__ f,
    const float* __restrict__ gate, const float* __restrict__ rms)
{
    const int r = blockIdx.x, tid = threadIdx.x;
    const int h = tid >> 4;
    const float g = gate[(size_t)r * 16 + h] / rms[(r >> 11) * 16 + h];
    float4* op = (float4*)(o + (size_t)r * C_DIM) + tid;
    const float4 fv = ((const float4*)(f + (size_t)r * C_DIM))[tid];
    float4 ov = *op;
    ov.x += g * fv.x; ov.y += g * fv.y; ov.z += g * fv.z; ov.w += g * fv.w;
    *op = ov;
}

// ---------------- launch ----------------
extern "C" void kernel_launch(void* const* d_in, const int* in_sizes, int n_in,
                              void* d_out, int out_size)
{
    const float* x     = (const float*)d_in[0];
    const float* emb   = (const float*)d_in[1];
    const float* W_emb = (const float*)d_in[2];
    const float* b_emb = (const float*)d_in[3];
    const float* ln_w  = (const float*)d_in[4];
    const float* ln_b  = (const float*)d_in[5];
    const float* W_f   = (const float*)d_in[6];
    const float* b_f   = (const float*)d_in[7];
    const float* qn_w  = (const float*)d_in[8];
    const float* qn_b  = (const float*)d_in[9];
    const float* kn_w  = (const float*)d_in[10];
    const float* kn_b  = (const float*)d_in[11];
    const float* W_ao  = (const float*)d_in[12];
    const float* b_ao  = (const float*)d_in[13];
    const float* W_mo  = (const float*)d_in[14];
    const float* b_mo  = (const float*)d_in[15];
    const float* Wm_in = (const float*)d_in[16];
    const float* bm_in = (const float*)d_in[17];
    const float* Wm_out= (const float*)d_in[18];
    const float* bm_out= (const float*)d_in[19];
    const float* W_g   = (const float*)d_in[20];
    const float* b_g   = (const float*)d_in[21];
    float* out = (float*)d_out;

    float *se, *xn, *fused, *o, *vg, *h2, *Wmo, *f, *gate, *rms, *x2;
    cudaGetSymbolAddress((void**)&se,    g_se);
    cudaGetSymbolAddress((void**)&xn,    g_xn);
    cudaGetSymbolAddress((void**)&fused, g_fused);
    cudaGetSymbolAddress((void**)&o,     g_o);
    cudaGetSymbolAddress((void**)&vg,    g_vg);
    cudaGetSymbolAddress((void**)&h2,    g_h2);
    cudaGetSymbolAddress((void**)&Wmo,   g_Wmo);
    cudaGetSymbolAddress((void**)&f,     g_f);
    cudaGetSymbolAddress((void**)&gate,  g_gate);
    cudaGetSymbolAddress((void**)&rms,   g_rms);
    cudaGetSymbolAddress((void**)&x2,    g_x2);

    const int MB = T_ROWS / 128;  // 64
    dim3 blk(256);

    // 1) se = emb @ W_emb + b_emb
    sgemm_k<false, false><<<dim3(SE_N / 128, MB), blk>>>(
        emb, C_DIM, W_emb, SE_N, b_emb, nullptr, 0, se, SE_N, SE_N, C_DIM);

    // 2) xn = LN(x)*(1+scale)+shift
    k_lnmod<<<T_ROWS, blk>>>(x, ln_w, ln_b, se, xn);

    // 3) fused = xn @ W_f + b_f
    sgemm_k<false, false><<<dim3(FUSED_N / 128, MB), blk>>>(
        xn, C_DIM, W_f, FUSED_N, b_f, nullptr, 0, fused, FUSED_N, FUSED_N, C_DIM);

    // 4) per-head LN of q,k in place
    k_qkln<<<T_ROWS * H_DIM / 8, blk>>>(fused, qn_w, qn_b, kn_w, kn_b);

    // 5) flash attention -> o [B,N,H,D]
    cudaFuncSetAttribute(k_attn, cudaFuncAttributeMaxDynamicSharedMemorySize,
                         4 * 64 * APAD * (int)sizeof(float));
    k_attn<<<dim3(32, 64), blk, 4 * 64 * APAD * sizeof(float)>>>(fused, o);

    // 6) vg = qp @ Wm_in + bm_in  (qp = LN'd q, strided inside fused)
    sgemm_k<false, false><<<dim3((VG_N + 127) / 128, MB), blk>>>(
        fused, FUSED_N, Wm_in, VG_N, bm_in, nullptr, 0, vg, VG_N, VG_N, C_DIM);

    // 7) h2 = silu(g)*vv (padded), 8) pad Wm_out
    k_silu_h2<<<T_ROWS, blk>>>(vg, h2);
    k_padW<<<INNER_P, blk>>>(Wm_out, Wmo);

    // 9) f = h2 @ Wm_out + bm_out
    sgemm_k<false, false><<<dim3(C_DIM / 128, MB), blk>>>(
        h2, INNER_P, Wmo, C_DIM, bm_out, nullptr, 0, f, C_DIM, C_DIM, INNER_P);

    // 10) gate, 11) rms, 12) o += gate * f / rms
    k_gate<<<T_ROWS, blk>>>(x, W_g, b_g, gate);
    k_rms<<<4 * H_DIM, blk>>>(f, rms);
    k_combine<<<T_ROWS, blk>>>(o, f, gate, rms);

    // 13) x2 = x + o @ W_ao + b_ao
    sgemm_k<false, true><<<dim3(C_DIM / 128, MB), blk>>>(
        o, C_DIM, W_ao, C_DIM, b_ao, x, C_DIM, x2, C_DIM, C_DIM, C_DIM);

    // 14) out = x2 + silu(mlp_h) @ W_mo + b_mo
    sgemm_k<true, true><<<dim3(C_DIM / 128, MB), blk>>>(
        fused + 3 * C_DIM, FUSED_N, W_mo, C_DIM, b_mo, x2, C_DIM, out, C_DIM, C_DIM, MLP_DIM);
}

// round 2
// speedup vs baseline: 2.5203x; 2.5203x over previous
#include <cuda_runtime.h>
#include <math.h>
#include <stdint.h>

// Problem constants
#define T_ROWS   8192            // B*N
#define C_DIM    1024
#define H_DIM    16
#define D_DIM    64
#define FUSED_N  7168            // 3C + MLP
#define SE_N     2048
#define MLP_DIM  4096
#define INNER    2730
#define INNER_P  2752            // padded K (mult of 32)
#define VG_P     5504            // padded 2*INNER (mult of 128)

// ---------------- scratch (static device allocations) ----------------
__device__ float g_se   [T_ROWS * SE_N];
__device__ float g_xn   [T_ROWS * C_DIM];
__device__ float g_fused[(size_t)T_ROWS * FUSED_N];
__device__ float g_o    [T_ROWS * C_DIM];
__device__ float g_vg   [(size_t)T_ROWS * VG_P];
__device__ float g_h2   [(size_t)T_ROWS * INNER_P];
__device__ float g_mlps [(size_t)T_ROWS * MLP_DIM];
__device__ float g_f    [T_ROWS * C_DIM];
__device__ float g_gate [T_ROWS * H_DIM];
__device__ float g_rms  [4 * H_DIM];
__device__ float g_x2   [T_ROWS * C_DIM];
// tf32-converted (and padded) operands
__device__ float g_embt [T_ROWS * C_DIM];
__device__ float g_Wembt[C_DIM * SE_N];
__device__ float g_Wft  [(size_t)C_DIM * FUSED_N];
__device__ float g_Wmint[(size_t)C_DIM * VG_P];
__device__ float g_bmin [VG_P];
__device__ float g_Wmot [INNER_P * C_DIM];
__device__ float g_Waot [C_DIM * C_DIM];
__device__ float g_Wmo2t[MLP_DIM * C_DIM];

__device__ __forceinline__ float to_tf32(float x)
{
    uint32_t u;
    asm("cvt.rna.tf32.f32 %0, %1;" : "=r"(u) : "f"(x));
    return __uint_as_float(u);
}

// ---------------- convert + pad to tf32 ----------------
__global__ void __launch_bounds__(256) k_cvt(
    const float* __restrict__ in, float* __restrict__ out,
    int rows_in, int cols_in, int cols_out)
{
    const int r = blockIdx.y;
    const int c = blockIdx.x * 256 + threadIdx.x;
    if (c >= cols_out) return;
    float v = (c < cols_in && r < rows_in) ? in[(size_t)r * cols_in + c] : 0.f;
    out[(size_t)r * cols_out + c] = to_tf32(v);
}

// ---------------- tf32 tensor-core GEMM, 128x128x32, 3-stage cp.async ------
// Requires: M%128==0, N%128==0, K%32==0, all operands tf32-rounded already.
#define BM 128
#define BN 128
#define BK 32
#define NSTG 3
#define ASTR 36   // BK+4: (8m+k) pattern -> conflict-free A frag loads
#define BSTR 136  // BN+8: (8k+n) pattern -> conflict-free B frag loads
#define GSMEM ((NSTG*BM*ASTR + NSTG*BK*BSTR) * (int)sizeof(float))

template<bool RESID>
__global__ void __launch_bounds__(256) tgemm(
    const float* __restrict__ A, int lda,
    const float* __restrict__ B, int ldb,
    const float* __restrict__ bias,
    const float* __restrict__ R, int ldr,
    float* __restrict__ C, int ldc,
    int K)
{
    extern __shared__ float sh[];
    float* As = sh;                       // [NSTG][BM][ASTR]
    float* Bs = sh + NSTG * BM * ASTR;    // [NSTG][BK][BSTR]

    const int tid  = threadIdx.x;
    const int warp = tid >> 5, lane = tid & 31;
    const int wm = warp & 1, wn = warp >> 1;       // 2 x 4 warp grid
    const int lr = lane >> 2, lc = lane & 3;
    const int bx = blockIdx.x, by = blockIdx.y;

    // copy indices
    const int arow = tid >> 3;           // 0..31
    const int acol = (tid & 7) * 4;      // 0..28
    const int brow = tid >> 5;           // 0..7
    const int bcol = (tid & 31) * 4;     // 0..124

    const float* Ag = A + (size_t)(by * BM + arow) * lda + acol;
    const float* Bg = B + (size_t)brow * ldb + bx * BN + bcol;

    auto load_tile = [&](int stg, int k0) {
        float* Asd = As + stg * BM * ASTR;
        float* Bsd = Bs + stg * BK * BSTR;
#pragma unroll
        for (int i = 0; i < 4; i++) {
            uint32_t dst = (uint32_t)__cvta_generic_to_shared(
                Asd + (arow + i * 32) * ASTR + acol);
            const float* src = Ag + (size_t)(i * 32) * lda + k0;
            asm volatile("cp.async.cg.shared.global [%0], [%1], 16;\n"
                         :: "r"(dst), "l"(src));
        }
#pragma unroll
        for (int i = 0; i < 4; i++) {
            uint32_t dst = (uint32_t)__cvta_generic_to_shared(
                Bsd + (brow + i * 8) * BSTR + bcol);
            const float* src = Bg + (size_t)(k0 + i * 8) * ldb;
            asm volatile("cp.async.cg.shared.global [%0], [%1], 16;\n"
                         :: "r"(dst), "l"(src));
        }
        asm volatile("cp.async.commit_group;\n");
    };

    float acc[4][4][4];
#pragma unroll
    for (int mt = 0; mt < 4; mt++)
#pragma unroll
        for (int nt = 0; nt < 4; nt++)
#pragma unroll
            for (int i = 0; i < 4; i++) acc[mt][nt][i] = 0.f;

    const int ntiles = K / BK;
    load_tile(0, 0);
    load_tile(1, BK);
    asm volatile("cp.async.wait_group 1;\n");
    __syncthreads();

    for (int kt = 0; kt < ntiles; kt++) {
        const int stg = kt % NSTG;
        if (kt + 2 < ntiles) load_tile((kt + 2) % NSTG, (kt + 2) * BK);

        const float* Asd = As + stg * BM * ASTR + (wm * 64 + lr) * ASTR;
        const float* Bsd = Bs + stg * BK * BSTR + wn * 32 + lr;

#pragma unroll
        for (int kf = 0; kf < 4; kf++) {
            uint32_t af[4][4], bf[4][2];
#pragma unroll
            for (int mt = 0; mt < 4; mt++) {
                const float* p = Asd + mt * 16 * ASTR + kf * 8 + lc;
                af[mt][0] = __float_as_uint(p[0]);
                af[mt][1] = __float_as_uint(p[8 * ASTR]);
                af[mt][2] = __float_as_uint(p[4]);
                af[mt][3] = __float_as_uint(p[8 * ASTR + 4]);
            }
#pragma unroll
            for (int nt = 0; nt < 4; nt++) {
                const float* p = Bsd + (kf * 8 + lc) * BSTR + nt * 8;
                bf[nt][0] = __float_as_uint(p[0]);
                bf[nt][1] = __float_as_uint(p[4 * BSTR]);
            }
#pragma unroll
            for (int mt = 0; mt < 4; mt++)
#pragma unroll
                for (int nt = 0; nt < 4; nt++)
                    asm volatile(
                        "mma.sync.aligned.m16n8k8.row.col.f32.tf32.tf32.f32 "
                        "{%0,%1,%2,%3}, {%4,%5,%6,%7}, {%8,%9}, {%0,%1,%2,%3};\n"
                        : "+f"(acc[mt][nt][0]), "+f"(acc[mt][nt][1]),
                          "+f"(acc[mt][nt][2]), "+f"(acc[mt][nt][3])
                        : "r"(af[mt][0]), "r"(af[mt][1]),
                          "r"(af[mt][2]), "r"(af[mt][3]),
                          "r"(bf[nt][0]), "r"(bf[nt][1]));
        }
        if (kt + 1 < ntiles) {
            asm volatile("cp.async.wait_group 1;\n");
            __syncthreads();
        }
    }

    // epilogue
#pragma unroll
    for (int mt = 0; mt < 4; mt++) {
        const int gm = by * BM + wm * 64 + mt * 16 + lr;
#pragma unroll
        for (int nt = 0; nt < 4; nt++) {
            const int gn = bx * BN + wn * 32 + nt * 8 + lc * 2;
            const float b0 = bias[gn], b1 = bias[gn + 1];
            float2 v0 = make_float2(acc[mt][nt][0] + b0, acc[mt][nt][1] + b1);
            float2 v1 = make_float2(acc[mt][nt][2] + b0, acc[mt][nt][3] + b1);
            if (RESID) {
                float2 r0 = *(const float2*)(R + (size_t)gm * ldr + gn);
                float2 r1 = *(const float2*)(R + (size_t)(gm + 8) * ldr + gn);
                v0.x += r0.x; v0.y += r0.y;
                v1.x += r1.x; v1.y += r1.y;
            }
            *(float2*)(C + (size_t)gm * ldc + gn) = v0;
            *(float2*)(C + (size_t)(gm + 8) * ldc + gn) = v1;
        }
    }
}

// ---------------- block reduce helper ----------------
__device__ __forceinline__ float block_reduce_sum(float v)
{
    __shared__ float shr[32];
    const int lane = threadIdx.x & 31, wid = threadIdx.x >> 5;
#pragma unroll
    for (int o = 16; o > 0; o >>= 1) v += __shfl_xor_sync(0xffffffffu, v, o);
    __syncthreads();
    if (lane == 0) shr[wid] = v;
    __syncthreads();
    const int nw = blockDim.x >> 5;
    float r = (threadIdx.x < nw) ? shr[threadIdx.x] : 0.f;
    if (wid == 0) {
#pragma unroll
        for (int o = 16; o > 0; o >>= 1) r += __shfl_xor_sync(0xffffffffu, r, o);
        if (lane == 0) shr[0] = r;
    }
    __syncthreads();
    return shr[0];
}

// ---------------- LN(x)*(1+scale)+shift (tf32-rounded output) --------------
__global__ void __launch_bounds__(256) k_lnmod(
    const float* __restrict__ x, const float* __restrict__ lnw,
    const float* __restrict__ lnb, const float* __restrict__ se,
    float* __restrict__ xn)
{
    const int r = blockIdx.x, tid = threadIdx.x;
    const float4 v = ((const float4*)(x + (size_t)r * C_DIM))[tid];
    float s = v.x + v.y + v.z + v.w;
    s = block_reduce_sum(s);
    const float mu = s * (1.f / 1024.f);
    const float dx0 = v.x - mu, dx1 = v.y - mu, dx2 = v.z - mu, dx3 = v.w - mu;
    float q = dx0 * dx0 + dx1 * dx1 + dx2 * dx2 + dx3 * dx3;
    q = block_reduce_sum(q);
    const float rstd = rsqrtf(q * (1.f / 1024.f) + 1e-5f);
    const float4 w = ((const float4*)lnw)[tid];
    const float4 bb = ((const float4*)lnb)[tid];
    const float4 sc = ((const float4*)(se + (size_t)r * SE_N))[tid];
    const float4 sf = ((const float4*)(se + (size_t)r * SE_N + C_DIM))[tid];
    float4 out;
    out.x = to_tf32((dx0 * rstd * w.x + bb.x) * (1.f + sc.x) + sf.x);
    out.y = to_tf32((dx1 * rstd * w.y + bb.y) * (1.f + sc.y) + sf.y);
    out.z = to_tf32((dx2 * rstd * w.z + bb.z) * (1.f + sc.z) + sf.z);
    out.w = to_tf32((dx3 * rstd * w.w + bb.w) * (1.f + sc.w) + sf.w);
    ((float4*)(xn + (size_t)r * C_DIM))[tid] = out;
}

// ---------------- per-head LN of q,k (in place, tf32-rounded) --------------
__global__ void __launch_bounds__(256) k_qkln(
    float* __restrict__ fused,
    const float* __restrict__ qw, const float* __restrict__ qb,
    const float* __restrict__ kw, const float* __restrict__ kb)
{
    const int w = threadIdx.x >> 5, lane = threadIdx.x & 31;
    const int idx = blockIdx.x * 8 + w;
    const int r = idx >> 4, h = idx & 15;
    float* base = fused + (size_t)r * FUSED_N + h * D_DIM;
#pragma unroll
    for (int part = 0; part < 2; part++) {
        float* p = base + part * C_DIM;
        float v0 = p[lane], v1 = p[lane + 32];
        float s = v0 + v1;
#pragma unroll
        for (int o = 16; o > 0; o >>= 1) s += __shfl_xor_sync(0xffffffffu, s, o);
        const float mu = s * (1.f / 64.f);
        const float d0 = v0 - mu, d1 = v1 - mu;
        float q = d0 * d0 + d1 * d1;
#pragma unroll
        for (int o = 16; o > 0; o >>= 1) q += __shfl_xor_sync(0xffffffffu, q, o);
        const float rstd = rsqrtf(q * (1.f / 64.f) + 1e-5f);
        const float* ww = part ? kw : qw;
        const float* bb = part ? kb : qb;
        p[lane]      = to_tf32(d0 * rstd * ww[lane]      + bb[lane]);
        p[lane + 32] = to_tf32(d1 * rstd * ww[lane + 32] + bb[lane + 32]);
    }
}

// ---------------- flash attention, fp32, 64x64 tiles ----------------
#define APAD 68
__global__ void __launch_bounds__(256) k_attn(
    const float* __restrict__ fused, float* __restrict__ o)
{
    extern __shared__ float sh[];
    float* Qs = sh;
    float* Ks = sh + 64 * APAD;
    float* Vs = sh + 2 * 64 * APAD;
    float* Ps = sh + 3 * 64 * APAD;

    const int qt = blockIdx.x;
    const int bh = blockIdx.y;
    const int b = bh >> 4, h = bh & 15;
    const int tid = threadIdx.x;
    const int tx = tid & 15, ty = tid >> 4;

    const float* qbase = fused + (size_t)(b * 2048 + qt * 64) * FUSED_N + h * D_DIM;
    for (int idx = tid; idx < 4096; idx += 256) {
        const int i = idx >> 6, d = idx & 63;
        Qs[d * APAD + i] = qbase[(size_t)i * FUSED_N + d] * 0.125f;
    }

    float m[4], l[4], oa[4][4];
#pragma unroll
    for (int ii = 0; ii < 4; ii++) {
        m[ii] = -1e30f; l[ii] = 0.f;
#pragma unroll
        for (int dd = 0; dd < 4; dd++) oa[ii][dd] = 0.f;
    }
    __syncthreads();

    for (int kt = 0; kt < 32; kt++) {
        const float* kbase = fused + (size_t)(b * 2048 + kt * 64) * FUSED_N + C_DIM + h * D_DIM;
        const float* vbase = kbase + C_DIM;
        for (int idx = tid; idx < 4096; idx += 256) {
            const int j = idx >> 6, d = idx & 63;
            Ks[d * APAD + j] = kbase[(size_t)j * FUSED_N + d];
            Vs[j * APAD + d] = vbase[(size_t)j * FUSED_N + d];
        }
        __syncthreads();

        float s[4][4];
#pragma unroll
        for (int ii = 0; ii < 4; ii++)
#pragma unroll
            for (int jj = 0; jj < 4; jj++) s[ii][jj] = 0.f;

#pragma unroll 16
        for (int d = 0; d < 64; d++) {
            const float4 a  = *(const float4*)&Qs[d * APAD + ty * 4];
            const float4 bq = *(const float4*)&Ks[d * APAD + tx * 4];
            const float av[4] = {a.x, a.y, a.z, a.w};
            const float bv[4] = {bq.x, bq.y, bq.z, bq.w};
#pragma unroll
            for (int ii = 0; ii < 4; ii++)
#pragma unroll
                for (int jj = 0; jj < 4; jj++)
                    s[ii][jj] += av[ii] * bv[jj];
        }

#pragma unroll
        for (int ii = 0; ii < 4; ii++) {
            float rm = fmaxf(fmaxf(s[ii][0], s[ii][1]), fmaxf(s[ii][2], s[ii][3]));
#pragma unroll
            for (int off = 1; off < 16; off <<= 1)
                rm = fmaxf(rm, __shfl_xor_sync(0xffffffffu, rm, off));
            const float mn = fmaxf(m[ii], rm);
            const float alpha = __expf(m[ii] - mn);
            m[ii] = mn;
            float rs = 0.f;
#pragma unroll
            for (int jj = 0; jj < 4; jj++) {
                const float p = __expf(s[ii][jj] - mn);
                s[ii][jj] = p; rs += p;
            }
#pragma unroll
            for (int off = 1; off < 16; off <<= 1)
                rs += __shfl_xor_sync(0xffffffffu, rs, off);
            l[ii] = l[ii] * alpha + rs;
#pragma unroll
            for (int dd = 0; dd < 4; dd++) oa[ii][dd] *= alpha;
        }

#pragma unroll
        for (int ii = 0; ii < 4; ii++)
            *(float4*)&Ps[(ty * 4 + ii) * APAD + tx * 4] =
                make_float4(s[ii][0], s[ii][1], s[ii][2], s[ii][3]);
        __syncthreads();

#pragma unroll 4
        for (int j4 = 0; j4 < 16; j4++) {
            float4 pv[4], vr[4];
#pragma unroll
            for (int ii = 0; ii < 4; ii++)
                pv[ii] = *(const float4*)&Ps[(ty * 4 + ii) * APAD + j4 * 4];
#pragma unroll
            for (int jj = 0; jj < 4; jj++)
                vr[jj] = *(const float4*)&Vs[(j4 * 4 + jj) * APAD + tx * 4];
#pragma unroll
            for (int ii = 0; ii < 4; ii++) {
                oa[ii][0] += pv[ii].x * vr[0].x + pv[ii].y * vr[1].x + pv[ii].z * vr[2].x + pv[ii].w * vr[3].x;
                oa[ii][1] += pv[ii].x * vr[0].y + pv[ii].y * vr[1].y + pv[ii].z * vr[2].y + pv[ii].w * vr[3].y;
                oa[ii][2] += pv[ii].x * vr[0].z + pv[ii].y * vr[1].z + pv[ii].z * vr[2].z + pv[ii].w * vr[3].z;
                oa[ii][3] += pv[ii].x * vr[0].w + pv[ii].y * vr[1].w + pv[ii].z * vr[2].w + pv[ii].w * vr[3].w;
            }
        }
        __syncthreads();
    }

    float* obase = o + (size_t)(b * 2048 + qt * 64) * C_DIM + h * D_DIM;
#pragma unroll
    for (int ii = 0; ii < 4; ii++) {
        const float inv = 1.f / l[ii];
        *(float4*)&obase[(size_t)(ty * 4 + ii) * C_DIM + tx * 4] =
            make_float4(oa[ii][0] * inv, oa[ii][1] * inv, oa[ii][2] * inv, oa[ii][3] * inv);
    }
}

// ---------------- h2 = silu(g)*vv, zero padded, tf32 ----------------
__global__ void __launch_bounds__(256) k_silu_h2(
    const float* __restrict__ vg, float* __restrict__ h2)
{
    const int r = blockIdx.x;
    const float* vr = vg + (size_t)r * VG_P;
    float* hr = h2 + (size_t)r * INNER_P;
    for (int c = threadIdx.x; c < INNER_P; c += 256) {
        float out = 0.f;
        if (c < INNER) {
            const float vv = vr[c];
            const float g = vr[INNER + c];
            out = to_tf32(vv * g / (1.f + __expf(-g)));
        }
        hr[c] = out;
    }
}

// ---------------- mlps = tf32(silu(mlp_h)) ----------------
__global__ void __launch_bounds__(256) k_silu_mlp(
    const float* __restrict__ fused, float* __restrict__ mlps)
{
    const int r = blockIdx.x;
    const float* src = fused + (size_t)r * FUSED_N + 3 * C_DIM;
    float* dst = mlps + (size_t)r * MLP_DIM;
    for (int c = threadIdx.x; c < MLP_DIM; c += 256) {
        const float g = src[c];
        dst[c] = to_tf32(g / (1.f + __expf(-g)));
    }
}

// ---------------- gate = tanh(x @ W_g + b_g) ----------------
__global__ void __launch_bounds__(256) k_gate(
    const float* __restrict__ x, const float* __restrict__ Wg,
    const float* __restrict__ bg, float* __restrict__ gate)
{
    __shared__ float xs[1024];
    __shared__ float part[16][17];
    const int r = blockIdx.x, tid = threadIdx.x;
    *(float4*)&xs[tid * 4] = ((const float4*)(x + (size_t)r * C_DIM))[tid];
    __syncthreads();
    const int h = tid & 15, seg = tid >> 4;
    float s = 0.f;
#pragma unroll 8
    for (int c = seg * 64; c < seg * 64 + 64; c++) s += xs[c] * Wg[c * 16 + h];
    part[h][seg] = s;
    __syncthreads();
    if (tid < 16) {
        float t = bg[tid];
#pragma unroll
        for (int sg = 0; sg < 16; sg++) t += part[tid][sg];
        gate[(size_t)r * 16 + tid] = tanhf(t);
    }
}

// ---------------- rms[b,h] over (n,d) of f ----------------
__global__ void __launch_bounds__(256) k_rms(const float* __restrict__ f, float* __restrict__ rms)
{
    const int b = blockIdx.x >> 4, h = blockIdx.x & 15;
    float s = 0.f;
    for (int n = threadIdx.x; n < 2048; n += 256) {
        const float4* fp = (const float4*)(f + (size_t)(b * 2048 + n) * C_DIM + h * D_DIM);
#pragma unroll
        for (int d4 = 0; d4 < 16; d4++) {
            const float4 v = fp[d4];
            s += v.x * v.x + v.y * v.y + v.z * v.z + v.w * v.w;
        }
    }
    s = block_reduce_sum(s);
    if (threadIdx.x == 0)
        rms[blockIdx.x] = fmaxf(sqrtf(s * (1.f / 131072.f)), 1e-6f);
}

// ---------------- o = tf32(o + gate * f / rms) ----------------
__global__ void __launch_bounds__(256) k_combine(
    float* __restrict__ o, const float* __restrict__ f,
    const float* __restrict__ gate, const float* __restrict__ rms)
{
    const int r = blockIdx.x, tid = threadIdx.x;
    const int h = tid >> 4;
    const float g = gate[(size_t)r * 16 + h] / rms[(r >> 11) * 16 + h];
    float4* op = (float4*)(o + (size_t)r * C_DIM) + tid;
    const float4 fv = ((const float4*)(f + (size_t)r * C_DIM))[tid];
    float4 ov = *op;
    ov.x = to_tf32(ov.x + g * fv.x);
    ov.y = to_tf32(ov.y + g * fv.y);
    ov.z = to_tf32(ov.z + g * fv.z);
    ov.w = to_tf32(ov.w + g * fv.w);
    *op = ov;
}

// ---------------- launch ----------------
extern "C" void kernel_launch(void* const* d_in, const int* in_sizes, int n_in,
                              void* d_out, int out_size)
{
    const float* x     = (const float*)d_in[0];
    const float* emb   = (const float*)d_in[1];
    const float* W_emb = (const float*)d_in[2];
    const float* b_emb = (const float*)d_in[3];
    const float* ln_w  = (const float*)d_in[4];
    const float* ln_b  = (const float*)d_in[5];
    const float* W_f   = (const float*)d_in[6];
    const float* b_f   = (const float*)d_in[7];
    const float* qn_w  = (const float*)d_in[8];
    const float* qn_b  = (const float*)d_in[9];
    const float* kn_w  = (const float*)d_in[10];
    const float* kn_b  = (const float*)d_in[11];
    const float* W_ao  = (const float*)d_in[12];
    const float* b_ao  = (const float*)d_in[13];
    const float* W_mo  = (const float*)d_in[14];
    const float* b_mo  = (const float*)d_in[15];
    const float* Wm_in = (const float*)d_in[16];
    const float* bm_in = (const float*)d_in[17];
    const float* Wm_out= (const float*)d_in[18];
    const float* bm_out= (const float*)d_in[19];
    const float* W_g   = (const float*)d_in[20];
    const float* b_g   = (const float*)d_in[21];
    float* out = (float*)d_out;

    float *se, *xn, *fused, *o, *vg, *h2, *mlps, *f, *gate, *rms, *x2;
    float *embt, *Wembt, *Wft, *Wmint, *bmin, *Wmot, *Waot, *Wmo2t;
    cudaGetSymbolAddress((void**)&se,    g_se);
    cudaGetSymbolAddress((void**)&xn,    g_xn);
    cudaGetSymbolAddress((void**)&fused, g_fused);
    cudaGetSymbolAddress((void**)&o,     g_o);
    cudaGetSymbolAddress((void**)&vg,    g_vg);
    cudaGetSymbolAddress((void**)&h2,    g_h2);
    cudaGetSymbolAddress((void**)&mlps,  g_mlps);
    cudaGetSymbolAddress((void**)&f,     g_f);
    cudaGetSymbolAddress((void**)&gate,  g_gate);
    cudaGetSymbolAddress((void**)&rms,   g_rms);
    cudaGetSymbolAddress((void**)&x2,    g_x2);
    cudaGetSymbolAddress((void**)&embt,  g_embt);
    cudaGetSymbolAddress((void**)&Wembt, g_Wembt);
    cudaGetSymbolAddress((void**)&Wft,   g_Wft);
    cudaGetSymbolAddress((void**)&Wmint, g_Wmint);
    cudaGetSymbolAddress((void**)&bmin,  g_bmin);
    cudaGetSymbolAddress((void**)&Wmot,  g_Wmot);
    cudaGetSymbolAddress((void**)&Waot,  g_Waot);
    cudaGetSymbolAddress((void**)&Wmo2t, g_Wmo2t);

    cudaFuncSetAttribute(tgemm<false>, cudaFuncAttributeMaxDynamicSharedMemorySize, GSMEM);
    cudaFuncSetAttribute(tgemm<true>,  cudaFuncAttributeMaxDynamicSharedMemorySize, GSMEM);
    cudaFuncSetAttribute(k_attn, cudaFuncAttributeMaxDynamicSharedMemorySize,
                         4 * 64 * APAD * (int)sizeof(float));

    const int MB = T_ROWS / 128;  // 64
    dim3 blk(256);

    // --- weight / input tf32 conversions (graph-constant work) ---
    k_cvt<<<dim3(C_DIM / 256, T_ROWS), blk>>>(emb,    embt,  T_ROWS, C_DIM, C_DIM);
    k_cvt<<<dim3(SE_N / 256, C_DIM), blk>>>(W_emb,  Wembt, C_DIM, SE_N, SE_N);
    k_cvt<<<dim3(FUSED_N / 256, C_DIM), blk>>>(W_f, Wft,   C_DIM, FUSED_N, FUSED_N);
    k_cvt<<<dim3((VG_P + 255) / 256, C_DIM), blk>>>(Wm_in, Wmint, C_DIM, 2 * INNER, VG_P);
    k_cvt<<<dim3((VG_P + 255) / 256, 1), blk>>>(bm_in, bmin, 1, 2 * INNER, VG_P);
    k_cvt<<<dim3(C_DIM / 256, INNER_P), blk>>>(Wm_out, Wmot, INNER, C_DIM, C_DIM);
    k_cvt<<<dim3(C_DIM / 256, C_DIM), blk>>>(W_ao,  Waot,  C_DIM, C_DIM, C_DIM);
    k_cvt<<<dim3(C_DIM / 256, MLP_DIM), blk>>>(W_mo, Wmo2t, MLP_DIM, C_DIM, C_DIM);

    // 1) se = emb @ W_emb + b_emb
    tgemm<false><<<dim3(SE_N / 128, MB), blk, GSMEM>>>(
        embt, C_DIM, Wembt, SE_N, b_emb, nullptr, 0, se, SE_N, C_DIM);

    // 2) xn = LN(x)*(1+scale)+shift  (tf32)
    k_lnmod<<<T_ROWS, blk>>>(x, ln_w, ln_b, se, xn);

    // 3) fused = xn @ W_f + b_f
    tgemm<false><<<dim3(FUSED_N / 128, MB), blk, GSMEM>>>(
        xn, C_DIM, Wft, FUSED_N, b_f, nullptr, 0, fused, FUSED_N, C_DIM);

    // 4) per-head LN of q,k in place (tf32)
    k_qkln<<<T_ROWS * H_DIM / 8, blk>>>(fused, qn_w, qn_b, kn_w, kn_b);

    // 5) flash attention -> o [B,N,H,D]
    k_attn<<<dim3(32, 64), blk, 4 * 64 * APAD * sizeof(float)>>>(fused, o);

    // 6) vg = qp @ Wm_in + bm_in  (padded N)
    tgemm<false><<<dim3(VG_P / 128, MB), blk, GSMEM>>>(
        fused, FUSED_N, Wmint, VG_P, bmin, nullptr, 0, vg, VG_P, C_DIM);

    // 7) h2 = silu(g)*vv (tf32, K-padded); mlps = silu(mlp_h) (tf32)
    k_silu_h2<<<T_ROWS, blk>>>(vg, h2);
    k_silu_mlp<<<T_ROWS, blk>>>(fused, mlps);

    // 8) f = h2 @ Wm_out + bm_out
    tgemm<false><<<dim3(C_DIM / 128, MB), blk, GSMEM>>>(
        h2, INNER_P, Wmot, C_DIM, bm_out, nullptr, 0, f, C_DIM, INNER_P);

    // 9) gate, rms, combine (o finalized, tf32)
    k_gate<<<T_ROWS, blk>>>(x, W_g, b_g, gate);
    k_rms<<<4 * H_DIM, blk>>>(f, rms);
    k_combine<<<T_ROWS, blk>>>(o, f, gate, rms);

    // 10) x2 = x + o @ W_ao + b_ao
    tgemm<true><<<dim3(C_DIM / 128, MB), blk, GSMEM>>>(
        o, C_DIM, Waot, C_DIM, b_ao, x, C_DIM, x2, C_DIM, C_DIM);

    // 11) out = x2 + mlps @ W_mo + b_mo
    tgemm<true><<<dim3(C_DIM / 128, MB), blk, GSMEM>>>(
        mlps, MLP_DIM, Wmo2t, C_DIM, b_mo, x2, C_DIM, out, C_DIM, MLP_DIM);
}